// round 7
// baseline (speedup 1.0000x reference)
#include <cuda_runtime.h>
#include <cuda_bf16.h>
#include <cstdint>

#define TT 512
#define BATCH 128
#define IND 128
#define HH 1024
#define OUTD 64
#define NCTA 130
#define NTHR 256
#define KCH 32
#define NCHW 18                     // chunks per warp (half of 36)
#define NKS 72                      // 1152 / 16 k-steps

#define OFF_BIAS 0
#define OFF_ABUF 1024
#define WSLOT 8192                  // per-warp: 2 stages x (hi 2KB + lo 2KB)
#define OFF_BFRAG (OFF_ABUF + 8 * WSLOT)        // 66560
#define BFRAG_SZ (NKS * 4 * 32 * 16)            // 147456 (hi+lo interleaved)
#define SMEM_TOTAL (OFF_BFRAG + BFRAG_SZ)       // 214016

__device__ __align__(16) __nv_bfloat16 g_u_hi[(size_t)TT * BATCH * IND];
__device__ __align__(16) __nv_bfloat16 g_u_lo[(size_t)TT * BATCH * IND];
__device__ __align__(16) __nv_bfloat16 g_h_hi[2][BATCH * HH];
__device__ __align__(16) __nv_bfloat16 g_h_lo[2][BATCH * HH];
__device__ unsigned int g_bar_count = 0;
__device__ unsigned int g_bar_gen = 0;

__device__ __forceinline__ float sg(float x) { return __fdividef(1.0f, 1.0f + __expf(-x)); }
__device__ __forceinline__ float th(float x) { return __fdividef(2.0f, 1.0f + __expf(-2.0f * x)) - 1.0f; }

__device__ __forceinline__ uint32_t pkbf(float a, float b, uint32_t& lo) {
    __nv_bfloat16 ah = __float2bfloat16_rn(a), bh = __float2bfloat16_rn(b);
    __nv_bfloat16 al = __float2bfloat16_rn(a - __bfloat162float(ah));
    __nv_bfloat16 bl = __float2bfloat16_rn(b - __bfloat162float(bh));
    lo = (uint32_t)__bfloat16_as_ushort(al) | ((uint32_t)__bfloat16_as_ushort(bl) << 16);
    return (uint32_t)__bfloat16_as_ushort(ah) | ((uint32_t)__bfloat16_as_ushort(bh) << 16);
}

__device__ __forceinline__ uint32_t smem_u32(const void* p) {
    uint32_t a;
    asm("{ .reg .u64 t; cvta.to.shared.u64 t, %1; cvt.u32.u64 %0, t; }" : "=r"(a) : "l"(p));
    return a;
}

__device__ __forceinline__ void ldsm_x4(uint32_t* r, uint32_t addr) {
    asm volatile("ldmatrix.sync.aligned.m8n8.x4.shared.b16 {%0,%1,%2,%3}, [%4];"
        : "=r"(r[0]), "=r"(r[1]), "=r"(r[2]), "=r"(r[3]) : "r"(addr));
}

__device__ __forceinline__ void mma_bf16(float* d, const uint32_t* a, uint32_t b0, uint32_t b1) {
    asm volatile(
        "mma.sync.aligned.m16n8k16.row.col.f32.bf16.bf16.f32 "
        "{%0,%1,%2,%3}, {%4,%5,%6,%7}, {%8,%9}, {%0,%1,%2,%3};"
        : "+f"(d[0]), "+f"(d[1]), "+f"(d[2]), "+f"(d[3])
        : "r"(a[0]), "r"(a[1]), "r"(a[2]), "r"(a[3]), "r"(b0), "r"(b1));
}

__device__ __forceinline__ void grid_barrier_full(unsigned int& epoch) {
    __syncthreads();
    if (threadIdx.x == 0) {
        __threadfence();
        unsigned int target = epoch + 1;
        unsigned int arr = atomicAdd(&g_bar_count, 1u);
        if (arr == NCTA - 1) {
            atomicExch(&g_bar_count, 0u);
            __threadfence();
            atomicAdd(&g_bar_gen, 1u);
        } else {
            while ((int)(*(volatile unsigned int*)&g_bar_gen - target) < 0) __nanosleep(32);
        }
        epoch = target;
        __threadfence();
    }
    __syncthreads();
}

__device__ __forceinline__ void bar_arrive() {
    if (threadIdx.x == 0) {
        __threadfence();
        unsigned int arr = atomicAdd(&g_bar_count, 1u);
        if (arr == NCTA - 1) {
            atomicExch(&g_bar_count, 0u);
            __threadfence();
            atomicAdd(&g_bar_gen, 1u);
        }
    }
}
__device__ __forceinline__ void bar_wait(unsigned int target) {
    while ((int)(*(volatile unsigned int*)&g_bar_gen - target) < 0) { }
    __threadfence();
}

// per-warp chunk load: warp's 32 rows x 32 k, hi+lo -> 4+4 uint4 regs.
// tu selects the u timestep (chunks 0..3); hphase selects the h buffer
// (chunks >= 4). These are DISTINCT: at the drain step t=TT, tu is clamped
// to TT-1 but the h buffer must be (t & 1) — the R6 bug was conflating them.
__device__ __forceinline__ void load_chunk_w(int tu, int hphase, int c,
    int rowbase, int lane, uint4* vhi, uint4* vlo)
{
    const __nv_bfloat16 *srcH, *srcL;
    int rstride;
    if (c < 4) {
        size_t base = (size_t)tu * BATCH * IND + c * KCH;
        srcH = g_u_hi + base; srcL = g_u_lo + base; rstride = IND;
    } else {
        size_t base = (size_t)c * KCH - IND;
        srcH = g_h_hi[hphase] + base; srcL = g_h_lo[hphase] + base; rstride = HH;
    }
    const int o = lane & 3;
    const int rb = rowbase + (lane >> 2);
    #pragma unroll
    for (int i = 0; i < 4; ++i) {
        int row = rb + 8 * i;
        vhi[i] = __ldcg((const uint4*)(srcH + (size_t)row * rstride + o * 8));
        vlo[i] = __ldcg((const uint4*)(srcL + (size_t)row * rstride + o * 8));
    }
}

__global__ void __launch_bounds__(NTHR, 1)
lstm_mma(const float* __restrict__ u, const float* __restrict__ x0,
         const float* __restrict__ kfiz, const float* __restrict__ bfiz,
         const float* __restrict__ kr, const float* __restrict__ br,
         const float* __restrict__ wout, const float* __restrict__ bout,
         float* __restrict__ y)
{
    extern __shared__ char smem[];
    const int tid = threadIdx.x;
    const int bid = blockIdx.x;
    const int warp = tid >> 5, lane = tid & 31;
    const int mg = warp >> 1, kh = warp & 1;
    const int rowbase = mg * 32;
    const int gid = lane >> 2, tig = lane & 3;
    const uint32_t sb = smem_u32(smem);
    float* bias_s = (float*)(smem + OFF_BIAS);
    unsigned int* base_s = (unsigned int*)(smem + OFF_BIAS + 512);

    // ---- init: weights -> smem B fragments (hi/lo interleaved uint4) ----
    for (int idx = tid; idx < NKS * 4 * 32; idx += NTHR) {
        int l = idx & 31;
        int nt = (idx >> 5) & 3;
        int s = idx >> 7;
        int nloc = nt * 8 + (l >> 2);
        int k0 = s * 16 + (l & 3) * 2;
        float w[4];
        #pragma unroll
        for (int q = 0; q < 4; ++q) {
            int k = k0 + (q >> 1) * 8 + (q & 1);
            float v;
            if (bid < 128) {
                int g = nloc >> 3, hid = bid * 8 + (nloc & 7);
                v = (g < 3) ? kfiz[(size_t)k * 3072 + g * 1024 + hid]
                            : kr[(size_t)k * 1024 + hid];
            } else {
                int col = (bid - 128) * 32 + nloc;
                v = (k < IND) ? 0.0f : wout[(size_t)(k - IND) * OUTD + col];
            }
            w[q] = v;
        }
        uint32_t lo0, lo1;
        uint32_t h0 = pkbf(w[0], w[1], lo0);
        uint32_t h1 = pkbf(w[2], w[3], lo1);
        *(uint4*)(smem + OFF_BFRAG + (uint32_t)idx * 16) = make_uint4(h0, h1, lo0, lo1);
    }
    if (tid < 32) {
        float bv;
        if (bid < 128) {
            int g = tid >> 3, hid = bid * 8 + (tid & 7);
            bv = (g < 3) ? bfiz[g * 1024 + hid] : br[hid];
        } else bv = bout[(bid - 128) * 32 + tid];
        bias_s[tid] = bv;
    }

    // ---- init: u -> (t,b,k) bf16 hi/lo, grid-strided ----
    {
        const size_t UN = (size_t)TT * BATCH * IND;
        for (size_t i = (size_t)bid * NTHR + tid; i < UN; i += (size_t)NCTA * NTHR) {
            int b = (int)(i / (TT * IND));
            int rem = (int)(i % (TT * IND));
            float w = u[i];
            __nv_bfloat16 hi = __float2bfloat16_rn(w);
            size_t o = ((size_t)(rem / IND) * BATCH + b) * IND + (rem % IND);
            g_u_hi[o] = hi;
            g_u_lo[o] = __float2bfloat16_rn(w - __bfloat162float(hi));
        }
    }

    // ---- init: c0 (kh==0 warps), h0 -> g_h[0] ----
    float creg[2][4];
    if (bid < 128) {
        if (kh == 0) {
            #pragma unroll
            for (int m = 0; m < 2; ++m)
                #pragma unroll
                for (int q = 0; q < 4; ++q) {
                    int row = rowbase + m * 16 + gid + (q >> 1) * 8;
                    creg[m][q] = x0[(size_t)row * 2 * HH + HH + bid * 8 + tig * 2 + (q & 1)];
                }
        }
        if (tid < 128) {
            const float* xp = x0 + (size_t)tid * 2 * HH;
            uint32_t hh[4], ll[4];
            #pragma unroll
            for (int q = 0; q < 4; ++q)
                hh[q] = pkbf(xp[bid * 8 + 2 * q], xp[bid * 8 + 2 * q + 1], ll[q]);
            size_t ho = (size_t)tid * HH + bid * 8;
            __stcg((uint4*)(g_h_hi[0] + ho), make_uint4(hh[0], hh[1], hh[2], hh[3]));
            __stcg((uint4*)(g_h_lo[0] + ho), make_uint4(ll[0], ll[1], ll[2], ll[3]));
        }
    }

    unsigned int epoch = 0;
    if (tid == 0) epoch = *(volatile unsigned int*)&g_bar_gen;
    grid_barrier_full(epoch);
    if (tid == 0) *base_s = epoch;
    __syncthreads();
    const unsigned int base = *base_s;

    float bcol[4][2];
    #pragma unroll
    for (int nt = 0; nt < 4; ++nt) {
        bcol[nt][0] = bias_s[nt * 8 + tig * 2];
        bcol[nt][1] = bias_s[nt * 8 + tig * 2 + 1];
    }

    // ldsm addressing in 32x64B tile (SW64): per Mtile row-base + XOR const
    uint32_t amo[2], axc[2];
    const int ach = lane >> 4;           // 16B col-half within kstep
    {
        int rloc = (lane & 7) + ((lane >> 3) & 1) * 8;
        #pragma unroll
        for (int m = 0; m < 2; ++m) {
            int row = m * 16 + rloc;
            amo[m] = (uint32_t)row * 64;
            axc[m] = ((uint32_t)row * 8) & 0x30;
        }
    }
    // store offsets (per lane, swizzled)
    uint32_t soff[4];
    {
        int o = lane & 3;
        #pragma unroll
        for (int i = 0; i < 4; ++i) {
            uint32_t row = (uint32_t)(lane >> 2) + 8 * i;
            soff[i] = row * 64 + (((uint32_t)o * 16) ^ ((row * 8) & 0x30));
        }
    }

    const char* bf = smem + OFF_BFRAG;
    const uint32_t slot0 = sb + OFF_ABUF + warp * WSLOT;
    char* slotp = smem + OFF_ABUF + warp * WSLOT;
    char* partner = smem + OFF_ABUF + (warp ^ 1) * WSLOT;

    uint4 vhi[4], vlo[4];
    load_chunk_w(0, 0, kh, rowbase, lane, vhi, vlo);

    for (int t = 0; t <= TT; ++t) {
        const int tt = (t < TT) ? t : (TT - 1);   // u timestep (clamped)
        const int hp = t & 1;                     // h buffer phase (NOT clamped)

        float acc[2][4][4];
        #pragma unroll
        for (int m = 0; m < 2; ++m)
            #pragma unroll
            for (int nt = 0; nt < 4; ++nt)
                #pragma unroll
                for (int q = 0; q < 4; ++q) acc[m][nt][q] = 0.0f;

        for (int lc = 0; lc < NCHW; ++lc) {
            const uint32_t stg = (uint32_t)(lc & 1) * 4096;
            char* sp = slotp + stg;
            #pragma unroll
            for (int i = 0; i < 4; ++i) {
                *(uint4*)(sp + soff[i]) = vhi[i];
                *(uint4*)(sp + 2048 + soff[i]) = vlo[i];
            }
            __syncwarp();

            if (lc + 1 < NCHW) {
                if (lc + 1 == 2) bar_wait(base + t);   // h(t) published
                load_chunk_w(tt, hp, 2 * (lc + 1) + kh, rowbase, lane, vhi, vlo);
            } else if (t < TT) {
                int tn = (t + 1 < TT) ? (t + 1) : (TT - 1);
                load_chunk_w(tn, 0, kh, rowbase, lane, vhi, vlo);   // u chunk only
            }

            const uint32_t sbase = slot0 + stg;
            #pragma unroll
            for (int kk = 0; kk < 2; ++kk) {
                uint32_t o16 = ((uint32_t)(kk * 2 + ach)) * 16;
                uint32_t ah[2][4], al[2][4];
                #pragma unroll
                for (int m = 0; m < 2; ++m) {
                    uint32_t aa = sbase + amo[m] + (o16 ^ axc[m]);
                    ldsm_x4(ah[m], aa);
                    ldsm_x4(al[m], aa + 2048);
                }
                int s = 4 * lc + 2 * kh + kk;
                #pragma unroll
                for (int nt = 0; nt < 4; ++nt) {
                    uint4 bb = *(const uint4*)(bf + (uint32_t)((s * 4 + nt) * 32 + lane) * 16);
                    #pragma unroll
                    for (int m = 0; m < 2; ++m) {
                        mma_bf16(acc[m][nt], ah[m], bb.x, bb.y);
                        mma_bf16(acc[m][nt], ah[m], bb.z, bb.w);
                        mma_bf16(acc[m][nt], al[m], bb.x, bb.y);
                    }
                }
            }
        }

        // ---- cross-warp-pair reduction (kh=1 -> smem, kh=0 adds) ----
        if (kh == 1) {
            #pragma unroll
            for (int m = 0; m < 2; ++m)
                #pragma unroll
                for (int nt = 0; nt < 4; ++nt)
                    *(float4*)(slotp + (uint32_t)(m * 4 + nt) * 512 + lane * 16) =
                        make_float4(acc[m][nt][0], acc[m][nt][1], acc[m][nt][2], acc[m][nt][3]);
        }
        __syncthreads();

        if (kh == 0) {
            #pragma unroll
            for (int m = 0; m < 2; ++m)
                #pragma unroll
                for (int nt = 0; nt < 4; ++nt) {
                    float4 p = *(const float4*)(partner + (uint32_t)(m * 4 + nt) * 512 + lane * 16);
                    acc[m][nt][0] += p.x; acc[m][nt][1] += p.y;
                    acc[m][nt][2] += p.z; acc[m][nt][3] += p.w;
                }
            if (bid < 128) {
                if (t < TT) {
                    int p = (t + 1) & 1;
                    #pragma unroll
                    for (int m = 0; m < 2; ++m) {
                        float hv[4];
                        #pragma unroll
                        for (int q = 0; q < 4; ++q) {
                            int e = q & 1;
                            float fp = acc[m][0][q] + bcol[0][e];
                            float ip = acc[m][1][q] + bcol[1][e];
                            float zp = acc[m][2][q] + bcol[2][e];
                            float rp = acc[m][3][q] + bcol[3][e];
                            creg[m][q] = sg(fp) * creg[m][q] + sg(ip) * th(rp);
                            hv[q] = sg(zp) * th(creg[m][q]);
                        }
                        #pragma unroll
                        for (int qp = 0; qp < 2; ++qp) {
                            int row = rowbase + m * 16 + gid + qp * 8;
                            uint32_t lo;
                            uint32_t hi = pkbf(hv[qp * 2], hv[qp * 2 + 1], lo);
                            size_t o = (size_t)row * HH + bid * 8 + tig * 2;
                            __stcg((unsigned int*)&g_h_hi[p][o], hi);
                            __stcg((unsigned int*)&g_h_lo[p][o], lo);
                        }
                    }
                }
            } else if (t >= 1) {
                #pragma unroll
                for (int m = 0; m < 2; ++m)
                    #pragma unroll
                    for (int nt = 0; nt < 4; ++nt)
                        #pragma unroll
                        for (int qp = 0; qp < 2; ++qp) {
                            int row = rowbase + m * 16 + gid + qp * 8;
                            int gcol = (bid - 128) * 32 + nt * 8 + tig * 2;
                            float2 v = make_float2(acc[m][nt][qp * 2] + bcol[nt][0],
                                                   acc[m][nt][qp * 2 + 1] + bcol[nt][1]);
                            *(float2*)&y[((size_t)row * TT + (t - 1)) * OUTD + gcol] = v;
                        }
            }
        }

        __syncthreads();
        bar_arrive();
    }
}

extern "C" void kernel_launch(void* const* d_in, const int* in_sizes, int n_in,
                              void* d_out, int out_size) {
    (void)in_sizes; (void)n_in; (void)out_size;
    cudaFuncSetAttribute(lstm_mma, cudaFuncAttributeMaxDynamicSharedMemorySize, SMEM_TOTAL);
    lstm_mma<<<NCTA, NTHR, SMEM_TOTAL>>>(
        (const float*)d_in[0], (const float*)d_in[1], (const float*)d_in[2],
        (const float*)d_in[3], (const float*)d_in[4], (const float*)d_in[5],
        (const float*)d_in[6], (const float*)d_in[7], (float*)d_out);
}